// round 1
// baseline (speedup 1.0000x reference)
#include <cuda_runtime.h>
#include <cstddef>

// Problem constants (from reference setup_inputs)
#define NL 4            // layers (mean over this axis)
#define NB 32           // batch
#define NS 512          // sequence
#define ND 768          // hidden dim
#define MAX_SPAN 4

// Tiling
#define TILE_T 32                       // outputs t per block
#define DC 256                          // d-chunk per block
#define NROWS (TILE_T + MAX_SPAN)       // 36 rows staged (t0+1 .. t0+TILE_T+MAX_SPAN)
#define NTHREADS 256

__global__ __launch_bounds__(NTHREADS)
void lmencoder_fused_kernel(const float* __restrict__ hs,
                            const int*   __restrict__ spans,
                            const int*   __restrict__ masks,
                            float*       __restrict__ out)
{
    const int dchunk = blockIdx.x;     // 0..2
    const int ttile  = blockIdx.y;     // 0..15
    const int b      = blockIdx.z;     // 0..31
    const int d0 = dchunk * DC;
    const int t0 = ttile * TILE_T;
    const int s0 = t0 + 1;             // first staged row

    __shared__ float sm[NROWS][DC];    // 36*256*4 = 36 KB
    __shared__ int   warp_sums[NTHREADS / 32];
    __shared__ int   sh_mask_len;

    const int tid = threadIdx.x;

    // ---- mask_len = sum(masks[b, :]) (tiny; L2-resident after first block) ----
    int msum = 0;
    for (int s = tid; s < NS; s += NTHREADS) msum += masks[b * NS + s];
    #pragma unroll
    for (int off = 16; off; off >>= 1) msum += __shfl_down_sync(0xffffffffu, msum, off);
    if ((tid & 31) == 0) warp_sums[tid >> 5] = msum;
    __syncthreads();
    if (tid == 0) {
        int t = 0;
        #pragma unroll
        for (int w = 0; w < NTHREADS / 32; w++) t += warp_sums[w];
        sh_mask_len = t;
    }

    // ---- load + mean: stage x_lm rows [s0, s0+NROWS) for d-chunk into SMEM ----
    // Each iteration: one float4 per thread per layer (4x LDG.128, good MLP).
    constexpr int VEC = DC / 4;                  // 64 float4 per row
    for (int i = tid; i < NROWS * VEC; i += NTHREADS) {
        const int r = i / VEC;
        const int c = i % VEC;
        const int s = s0 + r;
        float4 acc = make_float4(0.f, 0.f, 0.f, 0.f);
        if (s < NS) {
            #pragma unroll
            for (int l = 0; l < NL; l++) {
                const float4 v = *reinterpret_cast<const float4*>(
                    &hs[(((size_t)l * NB + b) * NS + s) * ND + d0 + 4 * c]);
                acc.x += v.x; acc.y += v.y; acc.z += v.z; acc.w += v.w;
            }
            acc.x *= 0.25f; acc.y *= 0.25f; acc.z *= 0.25f; acc.w *= 0.25f;
        }
        *reinterpret_cast<float4*>(&sm[r][4 * c]) = acc;
    }
    __syncthreads();

    const int mask_len = sh_mask_len;

    // ---- span pool from SMEM; nk uniform per t (no divergence) ----
    for (int tt = 0; tt < TILE_T; tt++) {
        const int t = t0 + tt;
        // span_next[b,t] = lm_spans[b,t+1] (0 at the end)
        const int span = (t + 1 < NS) ? spans[b * NS + t + 1] : 0;
        int nk = 0;
        if (t < mask_len - 2) {
            nk = span;
            const int lim = NS - 1 - t;            // enforce idx = t+1+k < NS
            if (nk > lim) nk = lim;
            if (nk > MAX_SPAN) nk = MAX_SPAN;
            if (nk < 0) nk = 0;
        }
        float acc = 0.f;
        // rows needed: s = t+1+k  ->  smem row r = tt + k
        for (int k = 0; k < nk; k++) acc += sm[tt + k][tid];
        out[((size_t)b * NS + t) * ND + d0 + tid] = acc;   // coalesced 1KB store
    }
}

extern "C" void kernel_launch(void* const* d_in, const int* in_sizes, int n_in,
                              void* d_out, int out_size)
{
    const float* hs    = (const float*)d_in[0];   // (4,32,512,768) fp32
    const int*   spans = (const int*)  d_in[1];   // (32,512) int32
    const int*   masks = (const int*)  d_in[2];   // (32,512) int32
    float*       out   = (float*)d_out;           // (32,512,768) fp32

    dim3 grid(ND / DC, NS / TILE_T, NB);          // (3, 16, 32) = 1536 blocks
    lmencoder_fused_kernel<<<grid, NTHREADS>>>(hs, spans, masks, out);
}

// round 2
// speedup vs baseline: 1.3073x; 1.3073x over previous
#include <cuda_runtime.h>
#include <cstddef>

// Problem constants
#define NL 4
#define NB 32
#define NS 512
#define ND 768
#define MAX_SPAN 4

// Tiling
#define TILE_T 32
#define DC 256
#define NROWS (TILE_T + MAX_SPAN)        // 36 staged rows
#define NTHREADS 256
#define VEC (DC / 4)                     // 64 float4 per row
#define NITEMS ((NROWS * VEC) / NTHREADS) // 9 items per thread
#define LSTRIDE4 ((size_t)NB * NS * ND / 4) // layer stride in float4 units

__global__ __launch_bounds__(NTHREADS)
void lmencoder_fused2(const float* __restrict__ hs,
                      const int*   __restrict__ spans,
                      const int*   __restrict__ masks,
                      float*       __restrict__ out)
{
    const int dchunk = blockIdx.x;   // 0..2
    const int ty     = blockIdx.y;   // 0..7  (handles t-tiles ty and ty+8)
    const int b      = blockIdx.z;   // 0..31
    const int d0 = dchunk * DC;

    __shared__ float4 sm4[NROWS * VEC];          // 36 KB
    __shared__ int    sh_nk[TILE_T];
    __shared__ int    warp_sums[NTHREADS / 32];
    __shared__ int    sh_mask_len;

    const int tid = threadIdx.x;

    // ---- mask_len = sum(masks[b,:]) once per block ----
    int msum = 0;
    #pragma unroll
    for (int s = tid; s < NS; s += NTHREADS) msum += masks[b * NS + s];
    #pragma unroll
    for (int off = 16; off; off >>= 1) msum += __shfl_down_sync(0xffffffffu, msum, off);
    if ((tid & 31) == 0) warp_sums[tid >> 5] = msum;
    __syncthreads();
    if (tid == 0) {
        int t = 0;
        #pragma unroll
        for (int w = 0; w < NTHREADS / 32; w++) t += warp_sums[w];
        sh_mask_len = t;
    }
    __syncthreads();
    const int mask_len = sh_mask_len;

    const float4* base = reinterpret_cast<const float4*>(hs + ((size_t)b * NS) * ND + d0);

    #pragma unroll
    for (int half = 0; half < 2; half++) {
        const int t0 = (ty + 8 * half) * TILE_T;
        const int s0 = t0 + 1;

        if (half) __syncthreads();   // previous tile's pool reads must finish

        // ---- per-t span counts into SMEM (one LDG per t, once) ----
        if (tid < TILE_T) {
            const int t = t0 + tid;
            int nk = 0;
            if (t < mask_len - 2) {
                const int span = (t + 1 < NS) ? spans[b * NS + t + 1] : 0;
                nk = span;
                const int lim = NS - 1 - t;
                if (nk > lim) nk = lim;
                if (nk > MAX_SPAN) nk = MAX_SPAN;
                if (nk < 0) nk = 0;
            }
            sh_nk[tid] = nk;
        }

        // ---- load + mean, pair-batched: 8 independent LDG.128 in flight ----
        const float4 z = make_float4(0.f, 0.f, 0.f, 0.f);
        #pragma unroll
        for (int kp = 0; kp < NITEMS / 2; kp++) {        // 4 pairs
            const int i0 = tid + (2 * kp) * NTHREADS;
            const int i1 = tid + (2 * kp + 1) * NTHREADS;
            const int sA = s0 + (i0 >> 6);
            const int sB = s0 + (i1 >> 6);
            const float4* pA = base + (size_t)sA * (ND / 4) + (i0 & 63);
            const float4* pB = base + (size_t)sB * (ND / 4) + (i1 & 63);

            float4 a0 = z, a1 = z, a2 = z, a3 = z;
            float4 b0 = z, b1 = z, b2 = z, b3 = z;
            if (sA < NS) {
                a0 = pA[0];            a1 = pA[LSTRIDE4];
                a2 = pA[2 * LSTRIDE4]; a3 = pA[3 * LSTRIDE4];
            }
            if (sB < NS) {
                b0 = pB[0];            b1 = pB[LSTRIDE4];
                b2 = pB[2 * LSTRIDE4]; b3 = pB[3 * LSTRIDE4];
            }
            float4 accA, accB;
            accA.x = ((a0.x + a1.x) + (a2.x + a3.x)) * 0.25f;
            accA.y = ((a0.y + a1.y) + (a2.y + a3.y)) * 0.25f;
            accA.z = ((a0.z + a1.z) + (a2.z + a3.z)) * 0.25f;
            accA.w = ((a0.w + a1.w) + (a2.w + a3.w)) * 0.25f;
            accB.x = ((b0.x + b1.x) + (b2.x + b3.x)) * 0.25f;
            accB.y = ((b0.y + b1.y) + (b2.y + b3.y)) * 0.25f;
            accB.z = ((b0.z + b1.z) + (b2.z + b3.z)) * 0.25f;
            accB.w = ((b0.w + b1.w) + (b2.w + b3.w)) * 0.25f;
            sm4[i0] = accA;
            sm4[i1] = accB;
        }
        {   // odd 9th item
            const int i0 = tid + (NITEMS - 1) * NTHREADS;
            const int sA = s0 + (i0 >> 6);
            const float4* pA = base + (size_t)sA * (ND / 4) + (i0 & 63);
            float4 a0 = z, a1 = z, a2 = z, a3 = z;
            if (sA < NS) {
                a0 = pA[0];            a1 = pA[LSTRIDE4];
                a2 = pA[2 * LSTRIDE4]; a3 = pA[3 * LSTRIDE4];
            }
            float4 accA;
            accA.x = ((a0.x + a1.x) + (a2.x + a3.x)) * 0.25f;
            accA.y = ((a0.y + a1.y) + (a2.y + a3.y)) * 0.25f;
            accA.z = ((a0.z + a1.z) + (a2.z + a3.z)) * 0.25f;
            accA.w = ((a0.w + a1.w) + (a2.w + a3.w)) * 0.25f;
            sm4[i0] = accA;
        }
        __syncthreads();

        // ---- pool: float4 per thread, nk uniform per warp, float4 stores ----
        const int c4 = tid & 63;      // float4 column within d-chunk
        const int tg = tid >> 6;      // 0..3
        #pragma unroll
        for (int j = 0; j < TILE_T / 4; j++) {   // 8 t's per thread
            const int tt = tg * 8 + j;
            const int nk = sh_nk[tt];
            float4 acc = make_float4(0.f, 0.f, 0.f, 0.f);
            for (int k = 0; k < nk; k++) {       // rows tt..tt+3 (s = t+1+k)
                const float4 v = sm4[(tt + k) * VEC + c4];
                acc.x += v.x; acc.y += v.y; acc.z += v.z; acc.w += v.w;
            }
            *reinterpret_cast<float4*>(
                out + ((size_t)b * NS + (t0 + tt)) * ND + d0 + 4 * c4) = acc;
        }
    }
}

extern "C" void kernel_launch(void* const* d_in, const int* in_sizes, int n_in,
                              void* d_out, int out_size)
{
    const float* hs    = (const float*)d_in[0];   // (4,32,512,768) fp32
    const int*   spans = (const int*)  d_in[1];   // (32,512) int32
    const int*   masks = (const int*)  d_in[2];   // (32,512) int32
    float*       out   = (float*)d_out;           // (32,512,768) fp32

    dim3 grid(ND / DC, (NS / TILE_T) / 2, NB);    // (3, 8, 32) = 768 blocks
    lmencoder_fused2<<<grid, NTHREADS>>>(hs, spans, masks, out);
}

// round 3
// speedup vs baseline: 1.4080x; 1.0771x over previous
#include <cuda_runtime.h>
#include <cstddef>

// Problem constants
#define NL 4
#define NB 32
#define NS 512
#define ND 768
#define MAX_SPAN 4

// Tiling
#define TILE_T 32
#define DC 256
#define NROWS (TILE_T + MAX_SPAN)            // 36 staged rows
#define NTHREADS 256
#define VEC (DC / 4)                         // 64 float4 per row
#define NITEMS ((NROWS * VEC) / NTHREADS)    // 9 items per thread
#define LSTRIDE4 ((size_t)NB * NS * ND / 4)  // layer stride in float4
#define NTT (NS / TILE_T)                    // 16 t-tiles
#define NDC (ND / DC)                        // 3 d-chunks
#define NTILES (NB * NTT * NDC)              // 1536 work tiles
#define GRID 592                             // 4 blocks/SM x 148 SMs: ONE wave

__global__ __launch_bounds__(NTHREADS)
void lmencoder_fused3(const float* __restrict__ hs,
                      const int*   __restrict__ spans,
                      const int*   __restrict__ masks,
                      float*       __restrict__ out)
{
    __shared__ float4 sm4[NROWS * VEC];      // 36 KB
    __shared__ int    sh_nk[TILE_T];
    __shared__ int    warp_sums[NTHREADS / 32];
    __shared__ int    sh_mask_len;

    const int tid = threadIdx.x;
    const float4 z = make_float4(0.f, 0.f, 0.f, 0.f);
    bool first = true;

    for (int tile = blockIdx.x; tile < NTILES; tile += GRID) {
        // tile order: b*48 + dchunk*16 + ttile  (adjacent ids share halo rows)
        const int b      = tile / (NTT * NDC);
        const int r      = tile - b * (NTT * NDC);
        const int dchunk = r >> 4;           // 0..2
        const int t0     = (r & 15) * TILE_T;
        const int s0     = t0 + 1;
        const int d0     = dchunk * DC;

        if (!first) __syncthreads();         // prev tile's pool reads done
        first = false;

        // ---- mask_len = sum(masks[b,:]) : one int2 per thread ----
        const int2 mv = reinterpret_cast<const int2*>(masks + b * NS)[tid];
        int msum = mv.x + mv.y;
        #pragma unroll
        for (int off = 16; off; off >>= 1)
            msum += __shfl_down_sync(0xffffffffu, msum, off);
        if ((tid & 31) == 0) warp_sums[tid >> 5] = msum;
        __syncthreads();
        if (tid == 0) {
            int t = 0;
            #pragma unroll
            for (int w = 0; w < NTHREADS / 32; w++) t += warp_sums[w];
            sh_mask_len = t;
        }
        __syncthreads();
        const int mask_len = sh_mask_len;

        // ---- per-t span counts (one LDG per t) ----
        if (tid < TILE_T) {
            const int t = t0 + tid;
            int nk = 0;
            if (t < mask_len - 2) {
                const int span = (t + 1 < NS) ? spans[b * NS + t + 1] : 0;
                nk = span;
                const int lim = NS - 1 - t;
                if (nk > lim) nk = lim;
                if (nk > MAX_SPAN) nk = MAX_SPAN;
                if (nk < 0) nk = 0;
            }
            sh_nk[tid] = nk;
        }

        // ---- load + mean, pair-batched: 8 independent LDG.128 in flight ----
        const float4* base = reinterpret_cast<const float4*>(hs)
                             + ((size_t)b * NS) * (ND / 4) + (d0 >> 2);
        #pragma unroll
        for (int kp = 0; kp < NITEMS / 2; kp++) {            // 4 pairs
            const int i0 = tid + (2 * kp) * NTHREADS;
            const int i1 = tid + (2 * kp + 1) * NTHREADS;
            const int sA = s0 + (i0 >> 6);
            const int sB = s0 + (i1 >> 6);
            const float4* pA = base + (size_t)sA * (ND / 4) + (i0 & 63);
            const float4* pB = base + (size_t)sB * (ND / 4) + (i1 & 63);

            float4 a0 = z, a1 = z, a2 = z, a3 = z;
            float4 b0 = z, b1 = z, b2 = z, b3 = z;
            if (sA < NS) {
                a0 = pA[0];            a1 = pA[LSTRIDE4];
                a2 = pA[2 * LSTRIDE4]; a3 = pA[3 * LSTRIDE4];
            }
            if (sB < NS) {
                b0 = pB[0];            b1 = pB[LSTRIDE4];
                b2 = pB[2 * LSTRIDE4]; b3 = pB[3 * LSTRIDE4];
            }
            float4 accA, accB;
            accA.x = ((a0.x + a1.x) + (a2.x + a3.x)) * 0.25f;
            accA.y = ((a0.y + a1.y) + (a2.y + a3.y)) * 0.25f;
            accA.z = ((a0.z + a1.z) + (a2.z + a3.z)) * 0.25f;
            accA.w = ((a0.w + a1.w) + (a2.w + a3.w)) * 0.25f;
            accB.x = ((b0.x + b1.x) + (b2.x + b3.x)) * 0.25f;
            accB.y = ((b0.y + b1.y) + (b2.y + b3.y)) * 0.25f;
            accB.z = ((b0.z + b1.z) + (b2.z + b3.z)) * 0.25f;
            accB.w = ((b0.w + b1.w) + (b2.w + b3.w)) * 0.25f;
            sm4[i0] = accA;
            sm4[i1] = accB;
        }
        {   // odd 9th item
            const int i0 = tid + (NITEMS - 1) * NTHREADS;
            const int sA = s0 + (i0 >> 6);
            const float4* pA = base + (size_t)sA * (ND / 4) + (i0 & 63);
            float4 a0 = z, a1 = z, a2 = z, a3 = z;
            if (sA < NS) {
                a0 = pA[0];            a1 = pA[LSTRIDE4];
                a2 = pA[2 * LSTRIDE4]; a3 = pA[3 * LSTRIDE4];
            }
            float4 accA;
            accA.x = ((a0.x + a1.x) + (a2.x + a3.x)) * 0.25f;
            accA.y = ((a0.y + a1.y) + (a2.y + a3.y)) * 0.25f;
            accA.z = ((a0.z + a1.z) + (a2.z + a3.z)) * 0.25f;
            accA.w = ((a0.w + a1.w) + (a2.w + a3.w)) * 0.25f;
            sm4[i0] = accA;
        }
        __syncthreads();

        // ---- pool: float4/thread, nk uniform per warp, streaming stores ----
        const int c4 = tid & 63;
        const int tg = tid >> 6;
        #pragma unroll
        for (int j = 0; j < TILE_T / 4; j++) {
            const int tt = tg * 8 + j;
            const int nk = sh_nk[tt];
            float4 acc = z;
            for (int k = 0; k < nk; k++) {
                const float4 v = sm4[(tt + k) * VEC + c4];
                acc.x += v.x; acc.y += v.y; acc.z += v.z; acc.w += v.w;
            }
            __stcs(reinterpret_cast<float4*>(
                out + ((size_t)b * NS + (t0 + tt)) * ND + d0 + 4 * c4), acc);
        }
    }
}

extern "C" void kernel_launch(void* const* d_in, const int* in_sizes, int n_in,
                              void* d_out, int out_size)
{
    const float* hs    = (const float*)d_in[0];   // (4,32,512,768) fp32
    const int*   spans = (const int*)  d_in[1];   // (32,512) int32
    const int*   masks = (const int*)  d_in[2];   // (32,512) int32
    float*       out   = (float*)d_out;           // (32,512,768) fp32

    lmencoder_fused3<<<GRID, NTHREADS>>>(hs, spans, masks, out);
}

// round 4
// speedup vs baseline: 1.4154x; 1.0052x over previous
#include <cuda_runtime.h>
#include <cstddef>

// Problem constants
#define NL 4
#define NB 32
#define NS 512
#define ND 768
#define MAX_SPAN 4

// Tiling
#define TILE_T 32
#define DC 256
#define NROWS (TILE_T + MAX_SPAN)            // 36 staged rows
#define NTHREADS 256
#define VEC (DC / 4)                         // 64 float4 per row
#define NITEMS ((NROWS * VEC) / NTHREADS)    // 9 items per thread (3 triples)
#define LSTRIDE4 ((size_t)NB * NS * ND / 4)  // layer stride in float4
#define NTT (NS / TILE_T)                    // 16 t-tiles
#define NDC (ND / DC)                        // 3 d-chunks
#define NTILES (NB * NTT * NDC)              // 1536 work tiles
#define GRID 384                             // 4 tiles per block, exact

__device__ int g_nk[NB * NS];                // precomputed span counts

// ---- tiny precompute: nk[b,t] ----
__global__ __launch_bounds__(NS)
void nk_precompute(const int* __restrict__ spans, const int* __restrict__ masks)
{
    const int b   = blockIdx.x;
    const int tid = threadIdx.x;              // 0..511 = t
    __shared__ int wsum[NS / 32];
    __shared__ int sh_len;

    int m = masks[b * NS + tid];
    #pragma unroll
    for (int off = 16; off; off >>= 1) m += __shfl_down_sync(0xffffffffu, m, off);
    if ((tid & 31) == 0) wsum[tid >> 5] = m;
    __syncthreads();
    if (tid == 0) {
        int t = 0;
        #pragma unroll
        for (int w = 0; w < NS / 32; w++) t += wsum[w];
        sh_len = t;
    }
    __syncthreads();
    const int mask_len = sh_len;

    const int t = tid;
    int nk = 0;
    if (t < mask_len - 2) {
        const int span = (t + 1 < NS) ? spans[b * NS + t + 1] : 0;
        nk = span;
        const int lim = NS - 1 - t;
        if (nk > lim) nk = lim;
        if (nk > MAX_SPAN) nk = MAX_SPAN;
        if (nk < 0) nk = 0;
    }
    g_nk[b * NS + t] = nk;
}

// ---- accumulate 4 layers of one float4 item ----
#define LOAD4(p, v0, v1, v2, v3, s)                          \
    do {                                                     \
        if ((s) < NS) {                                      \
            v0 = __ldcs(p);                                  \
            v1 = __ldcs((p) + LSTRIDE4);                     \
            v2 = __ldcs((p) + 2 * LSTRIDE4);                 \
            v3 = __ldcs((p) + 3 * LSTRIDE4);                 \
        }                                                    \
    } while (0)

__global__ __launch_bounds__(NTHREADS)
void lmencoder_fused4(const float* __restrict__ hs,
                      float*       __restrict__ out)
{
    __shared__ float4 sm4[NROWS * VEC];      // 36 KB
    __shared__ int    sh_nk[TILE_T];

    const int tid = threadIdx.x;
    const float4 z = make_float4(0.f, 0.f, 0.f, 0.f);

    #pragma unroll 1
    for (int j = 0; j < NTILES / GRID; j++) {
        const int tile = blockIdx.x * (NTILES / GRID) + j;   // 4 consecutive tiles
        const int b      = tile / (NTT * NDC);
        const int r      = tile - b * (NTT * NDC);
        const int dchunk = r >> 4;           // 0..2
        const int t0     = (r & 15) * TILE_T;
        const int s0     = t0 + 1;
        const int d0     = dchunk * DC;

        if (j) __syncthreads();              // prev tile's pool reads done

        if (tid < TILE_T)                    // nk for this tile (L2-hot, 128B)
            sh_nk[tid] = g_nk[b * NS + t0 + tid];

        // ---- load + mean: 3 triples, 12 independent LDG.128 each ----
        const float4* base = reinterpret_cast<const float4*>(hs)
                             + ((size_t)b * NS) * (ND / 4) + (d0 >> 2);
        #pragma unroll
        for (int kt = 0; kt < NITEMS / 3; kt++) {
            const int i0 = tid + (3 * kt) * NTHREADS;
            const int i1 = tid + (3 * kt + 1) * NTHREADS;
            const int i2 = tid + (3 * kt + 2) * NTHREADS;
            const int sA = s0 + (i0 >> 6);
            const int sB = s0 + (i1 >> 6);
            const int sC = s0 + (i2 >> 6);
            const float4* pA = base + (size_t)sA * (ND / 4) + (i0 & 63);
            const float4* pB = base + (size_t)sB * (ND / 4) + (i1 & 63);
            const float4* pC = base + (size_t)sC * (ND / 4) + (i2 & 63);

            float4 a0 = z, a1 = z, a2 = z, a3 = z;
            float4 b0 = z, b1 = z, b2 = z, b3 = z;
            float4 c0 = z, c1 = z, c2 = z, c3 = z;
            LOAD4(pA, a0, a1, a2, a3, sA);
            LOAD4(pB, b0, b1, b2, b3, sB);
            LOAD4(pC, c0, c1, c2, c3, sC);

            float4 accA, accB, accC;
            accA.x = ((a0.x + a1.x) + (a2.x + a3.x)) * 0.25f;
            accA.y = ((a0.y + a1.y) + (a2.y + a3.y)) * 0.25f;
            accA.z = ((a0.z + a1.z) + (a2.z + a3.z)) * 0.25f;
            accA.w = ((a0.w + a1.w) + (a2.w + a3.w)) * 0.25f;
            accB.x = ((b0.x + b1.x) + (b2.x + b3.x)) * 0.25f;
            accB.y = ((b0.y + b1.y) + (b2.y + b3.y)) * 0.25f;
            accB.z = ((b0.z + b1.z) + (b2.z + b3.z)) * 0.25f;
            accB.w = ((b0.w + b1.w) + (b2.w + b3.w)) * 0.25f;
            accC.x = ((c0.x + c1.x) + (c2.x + c3.x)) * 0.25f;
            accC.y = ((c0.y + c1.y) + (c2.y + c3.y)) * 0.25f;
            accC.z = ((c0.z + c1.z) + (c2.z + c3.z)) * 0.25f;
            accC.w = ((c0.w + c1.w) + (c2.w + c3.w)) * 0.25f;
            sm4[i0] = accA;
            sm4[i1] = accB;
            sm4[i2] = accC;
        }
        __syncthreads();

        // ---- pool: float4/thread, nk uniform per warp, streaming stores ----
        const int c4 = tid & 63;
        const int tg = tid >> 6;
        #pragma unroll
        for (int q = 0; q < TILE_T / 4; q++) {
            const int tt = tg * 8 + q;
            const int nk = sh_nk[tt];
            float4 acc = z;
            for (int k = 0; k < nk; k++) {
                const float4 v = sm4[(tt + k) * VEC + c4];
                acc.x += v.x; acc.y += v.y; acc.z += v.z; acc.w += v.w;
            }
            __stcs(reinterpret_cast<float4*>(
                out + ((size_t)b * NS + (t0 + tt)) * ND + d0 + 4 * c4), acc);
        }
    }
}

extern "C" void kernel_launch(void* const* d_in, const int* in_sizes, int n_in,
                              void* d_out, int out_size)
{
    const float* hs    = (const float*)d_in[0];   // (4,32,512,768) fp32
    const int*   spans = (const int*)  d_in[1];   // (32,512) int32
    const int*   masks = (const int*)  d_in[2];   // (32,512) int32
    float*       out   = (float*)d_out;           // (32,512,768) fp32

    nk_precompute<<<NB, NS>>>(spans, masks);
    lmencoder_fused4<<<GRID, NTHREADS>>>(hs, out);
}

// round 6
// speedup vs baseline: 1.4237x; 1.0059x over previous
#include <cuda_runtime.h>
#include <cstddef>

// Problem constants
#define NL 4
#define NB 32
#define NS 512
#define ND 768
#define MAX_SPAN 4

#define ND4 (ND / 4)                         // 192 float4 per row
#define LSTRIDE4 ((size_t)NB * NS * ND / 4)  // layer stride in float4
#define NDC 6                                // 128-wide d slices
#define TCHUNK 64                            // t per warp
#define NTC (NS / TCHUNK)                    // 8 warps per (b,dc)
#define GRID (NB * NDC)                      // 192 blocks, all resident

__device__ int g_nk[NB * NS];                // precomputed span counts

// ---- tiny precompute: nk[b,t] ----
__global__ __launch_bounds__(NS)
void nk_precompute(const int* __restrict__ spans, const int* __restrict__ masks)
{
    const int b   = blockIdx.x;
    const int tid = threadIdx.x;             // 0..511 = t
    __shared__ int wsum[NS / 32];
    __shared__ int sh_len;

    int m = masks[b * NS + tid];
    #pragma unroll
    for (int off = 16; off; off >>= 1) m += __shfl_down_sync(0xffffffffu, m, off);
    if ((tid & 31) == 0) wsum[tid >> 5] = m;
    __syncthreads();
    if (tid == 0) {
        int t = 0;
        #pragma unroll
        for (int w = 0; w < NS / 32; w++) t += wsum[w];
        sh_len = t;
    }
    __syncthreads();
    const int mask_len = sh_len;

    const int t = tid;
    int nk = 0;
    if (t < mask_len - 2) {
        const int span = (t + 1 < NS) ? spans[b * NS + t + 1] : 0;
        nk = span;
        const int lim = NS - 1 - t;
        if (nk > lim) nk = lim;
        if (nk > MAX_SPAN) nk = MAX_SPAN;
        if (nk < 0) nk = 0;
    }
    g_nk[b * NS + t] = nk;
}

// ---- mean of 4 layers for row s (clamped addr, zero-select OOB) ----
__device__ __forceinline__ float4 mrow(const float4* __restrict__ base, int s)
{
    const int sc = s < NS - 1 ? s : NS - 1;
    const float4* p = base + (size_t)sc * ND4;
    const float4 v0 = p[0];
    const float4 v1 = p[LSTRIDE4];
    const float4 v2 = p[2 * LSTRIDE4];
    const float4 v3 = p[3 * LSTRIDE4];
    float4 r;
    r.x = ((v0.x + v1.x) + (v2.x + v3.x)) * 0.25f;
    r.y = ((v0.y + v1.y) + (v2.y + v3.y)) * 0.25f;
    r.z = ((v0.z + v1.z) + (v2.z + v3.z)) * 0.25f;
    r.w = ((v0.w + v1.w) + (v2.w + v3.w)) * 0.25f;
    if (s >= NS) { r.x = 0.f; r.y = 0.f; r.z = 0.f; r.w = 0.f; }
    return r;
}

// ---- pooled output for one t: sum of first nk of {A,B,C,D} ----
__device__ __forceinline__ void emit(float4* __restrict__ op, int nk,
                                     const float4& A, const float4& B,
                                     const float4& C, const float4& D)
{
    float4 acc = make_float4(0.f, 0.f, 0.f, 0.f);
    if (nk > 0) { acc.x += A.x; acc.y += A.y; acc.z += A.z; acc.w += A.w; }
    if (nk > 1) { acc.x += B.x; acc.y += B.y; acc.z += B.z; acc.w += B.w; }
    if (nk > 2) { acc.x += C.x; acc.y += C.y; acc.z += C.z; acc.w += C.w; }
    if (nk > 3) { acc.x += D.x; acc.y += D.y; acc.z += D.z; acc.w += D.w; }
    __stcs(op, acc);
}

__global__ __launch_bounds__(256, 2)
void lmencoder_warp(const float* __restrict__ hs, float* __restrict__ out)
{
    const int lane = threadIdx.x & 31;
    const int tc   = threadIdx.x >> 5;       // 0..7: t-chunk
    const int b    = blockIdx.x / NDC;
    const int dc   = blockIdx.x - b * NDC;   // 0..5: 128-wide d slice
    const int t0   = tc * TCHUNK;

    const float4* base = reinterpret_cast<const float4*>(hs)
                         + (size_t)b * NS * ND4 + dc * 32 + lane;
    float4* obase = reinterpret_cast<float4*>(out)
                    + (size_t)b * NS * ND4 + dc * 32 + lane;
    const int4* nkp = reinterpret_cast<const int4*>(g_nk + b * NS + t0);

    // prologue: window rows t0+1..t0+3, current group rows t0+4..t0+7
    float4 w1 = mrow(base, t0 + 1);
    float4 w2 = mrow(base, t0 + 2);
    float4 w3 = mrow(base, t0 + 3);
    float4 r4 = mrow(base, t0 + 4);
    float4 r5 = mrow(base, t0 + 5);
    float4 r6 = mrow(base, t0 + 6);
    float4 r7 = mrow(base, t0 + 7);

    #pragma unroll 1
    for (int g = 0; g < TCHUNK / 4; g++) {
        const int t = t0 + 4 * g;
        const int4 nk = nkp[g];              // uniform: L1 broadcast

        // issue next group's 16 independent LDG.128 BEFORE emitting
        // (last iter: rows clamp to 511 and are zero-selected — harmless)
        const float4 n4 = mrow(base, t + 8);
        const float4 n5 = mrow(base, t + 9);
        const float4 n6 = mrow(base, t + 10);
        const float4 n7 = mrow(base, t + 11);

        emit(obase + (size_t)(t + 0) * ND4, nk.x, w1, w2, w3, r4);
        emit(obase + (size_t)(t + 1) * ND4, nk.y, w2, w3, r4, r5);
        emit(obase + (size_t)(t + 2) * ND4, nk.z, w3, r4, r5, r6);
        emit(obase + (size_t)(t + 3) * ND4, nk.w, r4, r5, r6, r7);

        w1 = r5; w2 = r6; w3 = r7;
        r4 = n4; r5 = n5; r6 = n6; r7 = n7;
    }
}

extern "C" void kernel_launch(void* const* d_in, const int* in_sizes, int n_in,
                              void* d_out, int out_size)
{
    const float* hs    = (const float*)d_in[0];   // (4,32,512,768) fp32
    const int*   spans = (const int*)  d_in[1];   // (32,512) int32
    const int*   masks = (const int*)  d_in[2];   // (32,512) int32
    float*       out   = (float*)d_out;           // (32,512,768) fp32

    nk_precompute<<<NB, NS>>>(spans, masks);
    lmencoder_warp<<<GRID, 256>>>(hs, out);
}

// round 7
// speedup vs baseline: 1.5288x; 1.0738x over previous
#include <cuda_runtime.h>
#include <cstddef>

// Problem constants
#define NL 4
#define NB 32
#define NS 512
#define ND 768
#define MAX_SPAN 4

#define ND4 (ND / 4)                         // 192 float4 per row
#define LSTRIDE4 ((size_t)NB * NS * ND / 4)  // layer stride in float4
#define NDC 6                                // 128-wide d slices
#define TCHUNK 64                            // t per warp
#define GRID (NB * NDC)                      // 192 blocks, all resident

// ---- mean of 4 layers for row s (clamped addr, zero-select OOB) ----
__device__ __forceinline__ float4 mrow(const float4* __restrict__ base, int s)
{
    const int sc = s < NS - 1 ? s : NS - 1;
    const float4* p = base + (size_t)sc * ND4;
    const float4 v0 = p[0];
    const float4 v1 = p[LSTRIDE4];
    const float4 v2 = p[2 * LSTRIDE4];
    const float4 v3 = p[3 * LSTRIDE4];
    float4 r;
    r.x = ((v0.x + v1.x) + (v2.x + v3.x)) * 0.25f;
    r.y = ((v0.y + v1.y) + (v2.y + v3.y)) * 0.25f;
    r.z = ((v0.z + v1.z) + (v2.z + v3.z)) * 0.25f;
    r.w = ((v0.w + v1.w) + (v2.w + v3.w)) * 0.25f;
    if (s >= NS) { r.x = 0.f; r.y = 0.f; r.z = 0.f; r.w = 0.f; }
    return r;
}

// ---- pooled output for one t: sum of first nk of {A,B,C,D} ----
__device__ __forceinline__ void emit(float4* __restrict__ op, int nk,
                                     const float4& A, const float4& B,
                                     const float4& C, const float4& D)
{
    float4 acc = make_float4(0.f, 0.f, 0.f, 0.f);
    if (nk > 0) { acc.x += A.x; acc.y += A.y; acc.z += A.z; acc.w += A.w; }
    if (nk > 1) { acc.x += B.x; acc.y += B.y; acc.z += B.z; acc.w += B.w; }
    if (nk > 2) { acc.x += C.x; acc.y += C.y; acc.z += C.z; acc.w += C.w; }
    if (nk > 3) { acc.x += D.x; acc.y += D.y; acc.z += D.z; acc.w += D.w; }
    __stcs(op, acc);
}

// 4 groups of 4 outputs using the nk source register nkreg (per-lane, 2 t's each)
#define GROUP_BODY(nkreg, gofs)                                               \
    {                                                                         \
        const int t = t0 + 4 * g + (gofs);                                    \
        const int lo = 4 * (g + ((gofs) >> 2) - ((gofs) >> 2)) ;              \
        (void)lo;                                                             \
        const int nk0 = __shfl_sync(0xffffffffu, nkreg, 4 * gg + 0);          \
        const int nk1 = __shfl_sync(0xffffffffu, nkreg, 4 * gg + 1);          \
        const int nk2 = __shfl_sync(0xffffffffu, nkreg, 4 * gg + 2);          \
        const int nk3 = __shfl_sync(0xffffffffu, nkreg, 4 * gg + 3);          \
        const float4 n4 = mrow(base, t + 8);                                  \
        const float4 n5 = mrow(base, t + 9);                                  \
        const float4 n6 = mrow(base, t + 10);                                 \
        const float4 n7 = mrow(base, t + 11);                                 \
        emit(obase + (size_t)(t + 0) * ND4, nk0, w1, w2, w3, r4);             \
        emit(obase + (size_t)(t + 1) * ND4, nk1, w2, w3, r4, r5);             \
        emit(obase + (size_t)(t + 2) * ND4, nk2, w3, r4, r5, r6);             \
        emit(obase + (size_t)(t + 3) * ND4, nk3, r4, r5, r6, r7);             \
        w1 = r5; w2 = r6; w3 = r7;                                            \
        r4 = n4; r5 = n5; r6 = n6; r7 = n7;                                   \
    }

__global__ __launch_bounds__(256, 2)
void lmencoder_warp2(const float* __restrict__ hs,
                     const int*   __restrict__ spans,
                     const int*   __restrict__ masks,
                     float*       __restrict__ out)
{
    const int lane = threadIdx.x & 31;
    const int tc   = threadIdx.x >> 5;       // 0..7: t-chunk
    const int b    = blockIdx.x / NDC;
    const int dc   = blockIdx.x - b * NDC;   // 0..5: 128-wide d slice
    const int t0   = tc * TCHUNK;

    // ---- mask_len: 4 coalesced int4 per lane over masks[b,:] + warp reduce ----
    const int4* mrow4 = reinterpret_cast<const int4*>(masks + b * NS);
    int msum = 0;
    #pragma unroll
    for (int k = 0; k < 4; k++) {
        const int4 m = mrow4[lane + 32 * k];
        msum += (m.x + m.y) + (m.z + m.w);
    }
    #pragma unroll
    for (int off = 16; off; off >>= 1)
        msum += __shfl_xor_sync(0xffffffffu, msum, off);
    const int mask_len = msum;               // identical in all lanes

    // ---- per-lane nk for t = t0+lane (nkA) and t0+32+lane (nkB) ----
    int nkA, nkB;
    {
        const int tA = t0 + lane;
        const int sA = (tA + 1 < NS) ? spans[b * NS + tA + 1] : 0;
        int nk = 0;
        if (tA < mask_len - 2) {
            nk = sA;
            const int lim = NS - 1 - tA;
            if (nk > lim) nk = lim;
            if (nk > MAX_SPAN) nk = MAX_SPAN;
            if (nk < 0) nk = 0;
        }
        nkA = nk;
        const int tB = t0 + 32 + lane;
        const int sB = (tB + 1 < NS) ? spans[b * NS + tB + 1] : 0;
        nk = 0;
        if (tB < mask_len - 2) {
            nk = sB;
            const int lim = NS - 1 - tB;
            if (nk > lim) nk = lim;
            if (nk > MAX_SPAN) nk = MAX_SPAN;
            if (nk < 0) nk = 0;
        }
        nkB = nk;
    }

    const float4* base = reinterpret_cast<const float4*>(hs)
                         + (size_t)b * NS * ND4 + dc * 32 + lane;
    float4* obase = reinterpret_cast<float4*>(out)
                    + (size_t)b * NS * ND4 + dc * 32 + lane;

    // prologue: window rows t0+1..t0+3, current group rows t0+4..t0+7
    float4 w1 = mrow(base, t0 + 1);
    float4 w2 = mrow(base, t0 + 2);
    float4 w3 = mrow(base, t0 + 3);
    float4 r4 = mrow(base, t0 + 4);
    float4 r5 = mrow(base, t0 + 5);
    float4 r6 = mrow(base, t0 + 6);
    float4 r7 = mrow(base, t0 + 7);

    // first half: groups 0..7 use nkA (lanes 4g..4g+3 hold t0+4g..t0+4g+3)
    #pragma unroll 1
    for (int g = 0; g < 8; g++) {
        const int gg = g;
        GROUP_BODY(nkA, 0)
    }
    // second half: groups 8..15 use nkB (lanes 4(g-8)..)
    #pragma unroll 1
    for (int g = 8; g < 16; g++) {
        const int gg = g - 8;
        GROUP_BODY(nkB, 0)
    }
}

extern "C" void kernel_launch(void* const* d_in, const int* in_sizes, int n_in,
                              void* d_out, int out_size)
{
    const float* hs    = (const float*)d_in[0];   // (4,32,512,768) fp32
    const int*   spans = (const int*)  d_in[1];   // (32,512) int32
    const int*   masks = (const int*)  d_in[2];   // (32,512) int32
    float*       out   = (float*)d_out;           // (32,512,768) fp32

    lmencoder_warp2<<<GRID, 256>>>(hs, spans, masks, out);
}

// round 8
// speedup vs baseline: 1.5440x; 1.0099x over previous
#include <cuda_runtime.h>
#include <cstddef>

// Problem constants
#define NL 4
#define NB 32
#define NS 512
#define ND 768
#define MAX_SPAN 4

#define ND4 (ND / 4)                         // 192 float4 per row
#define LSTRIDE4 ((size_t)NB * NS * ND / 4)  // layer stride in float4
#define NDC 6                                // 128-wide d slices
#define TCHUNK 64                            // t per warp-tile
#define NTILES (NB * NDC * (NS / TCHUNK))    // 1536 warp-tiles
#define GRID 148                             // one block per SM
#define NWARPS 12                            // 384 threads

// ---- mean of 4 layers for row s (address clamp only; rows >= NS are
//      never accumulated because nk <= NS-1-t) ----
__device__ __forceinline__ float4 mrow(const float4* __restrict__ base, int s)
{
    const int sc = s < NS - 1 ? s : NS - 1;
    const float4* p = base + (size_t)sc * ND4;
    const float4 v0 = p[0];
    const float4 v1 = p[LSTRIDE4];
    const float4 v2 = p[2 * LSTRIDE4];
    const float4 v3 = p[3 * LSTRIDE4];
    float4 r;
    r.x = ((v0.x + v1.x) + (v2.x + v3.x)) * 0.25f;
    r.y = ((v0.y + v1.y) + (v2.y + v3.y)) * 0.25f;
    r.z = ((v0.z + v1.z) + (v2.z + v3.z)) * 0.25f;
    r.w = ((v0.w + v1.w) + (v2.w + v3.w)) * 0.25f;
    return r;
}

// ---- pooled output for one t: sum of first nk of {A,B,C,D} ----
__device__ __forceinline__ void emit(float4* __restrict__ op, int nk,
                                     const float4& A, const float4& B,
                                     const float4& C, const float4& D)
{
    float4 acc = make_float4(0.f, 0.f, 0.f, 0.f);
    if (nk > 0) { acc.x += A.x; acc.y += A.y; acc.z += A.z; acc.w += A.w; }
    if (nk > 1) { acc.x += B.x; acc.y += B.y; acc.z += B.z; acc.w += B.w; }
    if (nk > 2) { acc.x += C.x; acc.y += C.y; acc.z += C.z; acc.w += C.w; }
    if (nk > 3) { acc.x += D.x; acc.y += D.y; acc.z += D.z; acc.w += D.w; }
    __stcs(op, acc);
}

__device__ __forceinline__ int nk_for(int t, int mask_len, int span)
{
    int nk = 0;
    if (t < mask_len - 2) {
        nk = span;
        const int lim = NS - 1 - t;
        if (nk > lim) nk = lim;
        if (nk > MAX_SPAN) nk = MAX_SPAN;
        if (nk < 0) nk = 0;
    }
    return nk;
}

__global__ __launch_bounds__(GRID == 148 ? 384 : 384, 1)
void lmencoder_warp3(const float* __restrict__ hs,
                     const int*   __restrict__ spans,
                     const int*   __restrict__ masks,
                     float*       __restrict__ out)
{
    const int lane = threadIdx.x & 31;
    const int wid  = threadIdx.x >> 5;          // 0..11
    const int tile = blockIdx.x + GRID * wid;   // every SM: 10-11 working warps
    if (tile >= NTILES) return;

    const int b  = tile / (NDC * (NS / TCHUNK));           // /48
    const int r  = tile - b * (NDC * (NS / TCHUNK));
    const int dc = r >> 3;                       // 0..5
    const int t0 = (r & 7) * TCHUNK;

    const float4* base = reinterpret_cast<const float4*>(hs)
                         + (size_t)b * NS * ND4 + dc * 32 + lane;
    float4* obase = reinterpret_cast<float4*>(out)
                    + (size_t)b * NS * ND4 + dc * 32 + lane;

    // ---- issue the 28 prologue LDG.128 FIRST (DRAM busy from cycle ~0) ----
    float4 w1 = mrow(base, t0 + 1);
    float4 w2 = mrow(base, t0 + 2);
    float4 w3 = mrow(base, t0 + 3);
    float4 r4 = mrow(base, t0 + 4);
    float4 r5 = mrow(base, t0 + 5);
    float4 r6 = mrow(base, t0 + 6);
    float4 r7 = mrow(base, t0 + 7);

    // ---- mask_len + per-lane nk, overlapped with prologue load latency ----
    const int4* mrow4 = reinterpret_cast<const int4*>(masks + b * NS);
    int msum = 0;
    #pragma unroll
    for (int k = 0; k < 4; k++) {
        const int4 m = mrow4[lane + 32 * k];
        msum += (m.x + m.y) + (m.z + m.w);
    }
    #pragma unroll
    for (int off = 16; off; off >>= 1)
        msum += __shfl_xor_sync(0xffffffffu, msum, off);
    const int mask_len = msum;

    const int tA = t0 + lane;
    const int tB = t0 + 32 + lane;
    const int spA = (tA + 1 < NS) ? spans[b * NS + tA + 1] : 0;
    const int spB = (tB + 1 < NS) ? spans[b * NS + tB + 1] : 0;
    const int nkA = nk_for(tA, mask_len, spA);
    const int nkB = nk_for(tB, mask_len, spB);

    // ---- first half: groups 0..7 (nk from nkA, lanes 4g..4g+3) ----
    #pragma unroll 1
    for (int g = 0; g < 8; g++) {
        const int t = t0 + 4 * g;
        const int nk0 = __shfl_sync(0xffffffffu, nkA, 4 * g + 0);
        const int nk1 = __shfl_sync(0xffffffffu, nkA, 4 * g + 1);
        const int nk2 = __shfl_sync(0xffffffffu, nkA, 4 * g + 2);
        const int nk3 = __shfl_sync(0xffffffffu, nkA, 4 * g + 3);
        const float4 n4 = mrow(base, t + 8);
        const float4 n5 = mrow(base, t + 9);
        const float4 n6 = mrow(base, t + 10);
        const float4 n7 = mrow(base, t + 11);
        emit(obase + (size_t)(t + 0) * ND4, nk0, w1, w2, w3, r4);
        emit(obase + (size_t)(t + 1) * ND4, nk1, w2, w3, r4, r5);
        emit(obase + (size_t)(t + 2) * ND4, nk2, w3, r4, r5, r6);
        emit(obase + (size_t)(t + 3) * ND4, nk3, r4, r5, r6, r7);
        w1 = r5; w2 = r6; w3 = r7;
        r4 = n4; r5 = n5; r6 = n6; r7 = n7;
    }
    // ---- second half: groups 8..14 with prefetch ----
    #pragma unroll 1
    for (int g = 8; g < 15; g++) {
        const int t = t0 + 4 * g;
        const int gg = g - 8;
        const int nk0 = __shfl_sync(0xffffffffu, nkB, 4 * gg + 0);
        const int nk1 = __shfl_sync(0xffffffffu, nkB, 4 * gg + 1);
        const int nk2 = __shfl_sync(0xffffffffu, nkB, 4 * gg + 2);
        const int nk3 = __shfl_sync(0xffffffffu, nkB, 4 * gg + 3);
        const float4 n4 = mrow(base, t + 8);
        const float4 n5 = mrow(base, t + 9);
        const float4 n6 = mrow(base, t + 10);
        const float4 n7 = mrow(base, t + 11);
        emit(obase + (size_t)(t + 0) * ND4, nk0, w1, w2, w3, r4);
        emit(obase + (size_t)(t + 1) * ND4, nk1, w2, w3, r4, r5);
        emit(obase + (size_t)(t + 2) * ND4, nk2, w3, r4, r5, r6);
        emit(obase + (size_t)(t + 3) * ND4, nk3, r4, r5, r6, r7);
        w1 = r5; w2 = r6; w3 = r7;
        r4 = n4; r5 = n5; r6 = n6; r7 = n7;
    }
    // ---- peeled last group (g=15): no wasted prefetch ----
    {
        const int t = t0 + 60;
        const int nk0 = __shfl_sync(0xffffffffu, nkB, 28);
        const int nk1 = __shfl_sync(0xffffffffu, nkB, 29);
        const int nk2 = __shfl_sync(0xffffffffu, nkB, 30);
        const int nk3 = __shfl_sync(0xffffffffu, nkB, 31);
        emit(obase + (size_t)(t + 0) * ND4, nk0, w1, w2, w3, r4);
        emit(obase + (size_t)(t + 1) * ND4, nk1, w2, w3, r4, r5);
        emit(obase + (size_t)(t + 2) * ND4, nk2, w3, r4, r5, r6);
        emit(obase + (size_t)(t + 3) * ND4, nk3, r4, r5, r6, r7);
    }
}

extern "C" void kernel_launch(void* const* d_in, const int* in_sizes, int n_in,
                              void* d_out, int out_size)
{
    const float* hs    = (const float*)d_in[0];   // (4,32,512,768) fp32
    const int*   spans = (const int*)  d_in[1];   // (32,512) int32
    const int*   masks = (const int*)  d_in[2];   // (32,512) int32
    float*       out   = (float*)d_out;           // (32,512,768) fp32

    lmencoder_warp3<<<GRID, 384>>>(hs, spans, masks, out);
}